// round 16
// baseline (speedup 1.0000x reference)
#include <cuda_runtime.h>
#include <cuda_fp16.h>
#include <cstdint>

// ---------------------------------------------------------------------------
// CrossNetLayer on GB300 (sm_103a; PTX target compute_103 -> no tcgen05)
//   h = x @ W_enc + b_enc  -> mma.sync fp16 GEMM, fp32 accum.
//   cross layers closed-form, folded into the GEMM epilogue:
//     V_l = W @ w_l ; c_l = b_enc . w_l ; e_l = u_l . w_l ; u4 = sum b_l
//     d_l(row) = x_row . V_l + c_l ;  a <- a + a*d_l + e_l (a0=1)
//     out = a4 * h + u4
// Single fused kernel, warp-specialized:
//   CTAs [0,128): GEMM 128x64 tiles (spin on conv_done, then a4_done)
//   CTAs [128,144): producers — convert x (warps 0-3) + W/V (warps 4-7),
//                   then a4 after all-producer barrier.
// setup_kernel (1 block) zeroes sync counters + computes c/e/u4.
// ---------------------------------------------------------------------------

#define BDIM 1024
#define HDIM 1024
#define KDIM 1024
#define DEPTH 4

// Scratch (no cudaMalloc allowed)
__device__ __half  g_x16[BDIM * KDIM];
__device__ __half  g_w16[KDIM * HDIM];   // W in original [k][n] layout, fp16
__device__ float   g_V[DEPTH * KDIM];    // V[l][k] = W[k,:].w_l   (fp32)
__device__ float   g_e[DEPTH];           // e_l = u_l . w_l
__device__ float   g_c[DEPTH];           // c_l = b_enc . w_l
__device__ float   g_u4[HDIM];           // u4 = b0+b1+b2+b3
__device__ float   g_a4[BDIM];           // per-row output scale
__device__ int     g_sync[2];            // [0]=conv_done, [1]=a4_done

// ---------------------------------------------------------------------------
// helpers
// ---------------------------------------------------------------------------
__device__ __forceinline__ uint32_t smem_u32(const void* p) {
    uint32_t a;
    asm("{ .reg .u64 t; cvta.to.shared.u64 t, %1; cvt.u32.u64 %0, t; }"
        : "=r"(a) : "l"(p));
    return a;
}

__device__ __forceinline__ uint32_t swz(uint32_t off) {
    return off ^ ((off >> 3) & 0x70);   // SW128: 16B granule ^= row&7
}

__device__ __forceinline__ void cp_async16(uint32_t smem_addr, const void* gptr) {
    asm volatile("cp.async.cg.shared.global [%0], [%1], 16;"
                 :: "r"(smem_addr), "l"(gptr));
}

__device__ __forceinline__ void ldsm_x4(uint32_t* r, uint32_t addr) {
    asm volatile("ldmatrix.sync.aligned.m8n8.x4.shared.b16 {%0,%1,%2,%3}, [%4];"
                 : "=r"(r[0]), "=r"(r[1]), "=r"(r[2]), "=r"(r[3]) : "r"(addr));
}

__device__ __forceinline__ void ldsm_x4_t(uint32_t* r, uint32_t addr) {
    asm volatile("ldmatrix.sync.aligned.m8n8.x4.trans.shared.b16 {%0,%1,%2,%3}, [%4];"
                 : "=r"(r[0]), "=r"(r[1]), "=r"(r[2]), "=r"(r[3]) : "r"(addr));
}

__device__ __forceinline__ void mma_f16(float* d, const uint32_t* a, const uint32_t* b) {
    asm volatile(
        "mma.sync.aligned.m16n8k16.row.col.f32.f16.f16.f32 "
        "{%0,%1,%2,%3}, {%4,%5,%6,%7}, {%8,%9}, {%0,%1,%2,%3};"
        : "+f"(d[0]), "+f"(d[1]), "+f"(d[2]), "+f"(d[3])
        : "r"(a[0]), "r"(a[1]), "r"(a[2]), "r"(a[3]), "r"(b[0]), "r"(b[1]));
}

__device__ __forceinline__ float dot4(float4 a, float4 b) {
    return a.x * b.x + a.y * b.y + a.z * b.z + a.w * b.w;
}

// ---------------------------------------------------------------------------
// setup_kernel: 1 block x 256 threads — zero sync counters; compute c,e,u4.
// ---------------------------------------------------------------------------
__global__ __launch_bounds__(256, 1) void setup_kernel(
    const float* __restrict__ b_enc,
    const float* __restrict__ ws, const float* __restrict__ bs)
{
    __shared__ float red[8][8];
    const int tid  = threadIdx.x;
    const int lane = tid & 31;
    const int wid  = tid >> 5;

    if (tid < 2) g_sync[tid] = 0;

    float r[7];   // c0,c1,c2,c3,e1,e2,e3
#pragma unroll
    for (int i = 0; i < 7; i++) r[i] = 0.f;
#pragma unroll
    for (int j = 0; j < 4; j++) {
        int c = tid * 4 + j;
        float be = b_enc[c];
        float b0 = bs[0 * HDIM + c];
        float b1 = bs[1 * HDIM + c];
        float b2 = bs[2 * HDIM + c];
        float b3 = bs[3 * HDIM + c];
        float w0 = ws[0 * HDIM + c];
        float w1 = ws[1 * HDIM + c];
        float w2 = ws[2 * HDIM + c];
        float w3 = ws[3 * HDIM + c];
        r[0] += be * w0;
        r[1] += be * w1;
        r[2] += be * w2;
        r[3] += be * w3;
        r[4] += b0 * w1;
        r[5] += (b0 + b1) * w2;
        r[6] += (b0 + b1 + b2) * w3;
        g_u4[c] = b0 + b1 + b2 + b3;
    }
#pragma unroll
    for (int o = 16; o > 0; o >>= 1)
#pragma unroll
        for (int i = 0; i < 7; i++)
            r[i] += __shfl_xor_sync(0xffffffffu, r[i], o);
    if (lane == 0) {
#pragma unroll
        for (int i = 0; i < 7; i++) red[wid][i] = r[i];
    }
    __syncthreads();
    if (tid == 0) {
        float s[7];
#pragma unroll
        for (int i = 0; i < 7; i++) {
            s[i] = 0.f;
#pragma unroll
            for (int w = 0; w < 8; w++) s[i] += red[w][i];
        }
        g_c[0] = s[0]; g_c[1] = s[1]; g_c[2] = s[2]; g_c[3] = s[3];
        g_e[0] = 0.0f; g_e[1] = s[4]; g_e[2] = s[5]; g_e[3] = s[6];
    }
}

// ---------------------------------------------------------------------------
// Fused kernel: grid 144 x 256 threads, 98KB smem, 1 CTA/SM.
// ---------------------------------------------------------------------------
#define GBM 128
#define GBN 64
#define GKC 128
#define NCHUNK (KDIM / GKC)     // 8

#define SUB_A 0
#define SUB_B 32768
#define STAGE_BYTES 49152
#define GEMM_SMEM (2 * STAGE_BYTES)   // 98304

__global__ __launch_bounds__(256, 1) void fused_kernel(
    const float* __restrict__ bias, const float* __restrict__ x,
    const float* __restrict__ W,    const float* __restrict__ ws,
    float* __restrict__ out)
{
    extern __shared__ char smem[];
    const int bid  = blockIdx.x;      // 0..143
    const int tid  = threadIdx.x;     // 0..255
    const int wid  = tid >> 5;        // 0..7
    const int lane = tid & 31;

    if (bid >= 128) {
        // ================= producer CTA =================
        const int p = bid - 128;      // 0..15, owns rows [p*64, p*64+64)

        // cache ws (4 x 1024 floats = 16KB) in smem
        float4* sws = (float4*)smem;
        const float4* gws = (const float4*)ws;
#pragma unroll
        for (int i = 0; i < 4; i++)
            sws[tid + i * 256] = gws[tid + i * 256];
        __syncthreads();

        if (wid < 4) {
            // ---- x convert: 16 rows per warp, 2 per iter (MLP=16) ----
            const float4* xb = (const float4*)x;
            const int rbase = p * 64 + wid * 16;
#pragma unroll
            for (int it = 0; it < 8; it++) {
                const int r0 = rbase + it * 2;
                const int r1 = r0 + 1;
                float4 v0[8], v1[8];
#pragma unroll
                for (int j = 0; j < 8; j++)
                    v0[j] = xb[(size_t)r0 * 256 + lane + j * 32];
#pragma unroll
                for (int j = 0; j < 8; j++)
                    v1[j] = xb[(size_t)r1 * 256 + lane + j * 32];
                __half2* d0 = (__half2*)(g_x16 + (size_t)r0 * KDIM);
                __half2* d1 = (__half2*)(g_x16 + (size_t)r1 * KDIM);
#pragma unroll
                for (int j = 0; j < 8; j++) {
                    int c2 = (lane + j * 32) * 2;
                    d0[c2]     = __floats2half2_rn(v0[j].x, v0[j].y);
                    d0[c2 + 1] = __floats2half2_rn(v0[j].z, v0[j].w);
                    d1[c2]     = __floats2half2_rn(v1[j].x, v1[j].y);
                    d1[c2 + 1] = __floats2half2_rn(v1[j].z, v1[j].w);
                }
            }
        } else {
            // ---- W convert + V dots: 16 rows per warp ----
            const float4* Wb = (const float4*)W;
            const int rbase = p * 64 + (wid - 4) * 16;
#pragma unroll
            for (int it = 0; it < 16; it++) {
                const int r = rbase + it;
                float4 a[8];
#pragma unroll
                for (int j = 0; j < 8; j++)
                    a[j] = Wb[(size_t)r * 256 + lane + j * 32];
                __half2* d = (__half2*)(g_w16 + (size_t)r * HDIM);
#pragma unroll
                for (int j = 0; j < 8; j++) {
                    int c2 = (lane + j * 32) * 2;
                    d[c2]     = __floats2half2_rn(a[j].x, a[j].y);
                    d[c2 + 1] = __floats2half2_rn(a[j].z, a[j].w);
                }
                float pl[4] = {0.f, 0.f, 0.f, 0.f};
#pragma unroll
                for (int j = 0; j < 8; j++)
#pragma unroll
                    for (int l = 0; l < 4; l++)
                        pl[l] += dot4(a[j], sws[l * 256 + lane + j * 32]);
#pragma unroll
                for (int o = 16; o > 0; o >>= 1)
#pragma unroll
                    for (int l = 0; l < 4; l++)
                        pl[l] += __shfl_xor_sync(0xffffffffu, pl[l], o);
                if (lane == 0) {
#pragma unroll
                    for (int l = 0; l < 4; l++)
                        g_V[l * KDIM + r] = pl[l];
                }
            }
        }

        __syncthreads();
        __threadfence();
        if (tid == 0) {
            atomicAdd(&g_sync[0], 1);
            while (atomicAdd(&g_sync[0], 0) < 16) { }
        }
        __syncthreads();
        __threadfence();

        // ---- a4 for rows [p*64, +64): V is complete now ----
        float4* sV = (float4*)smem;   // overwrite ws cache
        const float4* gV = (const float4*)g_V;
        __syncthreads();
#pragma unroll
        for (int i = 0; i < 4; i++)
            sV[tid + i * 256] = gV[tid + i * 256];
        __syncthreads();

        float cc[4], ee[4];
#pragma unroll
        for (int l = 0; l < 4; l++) { cc[l] = g_c[l]; ee[l] = g_e[l]; }

        const int rbase = p * 64 + wid * 8;
#pragma unroll
        for (int it = 0; it < 8; it++) {
            const int r = rbase + it;
            const float4* xr = (const float4*)(x + (size_t)r * KDIM);
            float4 xv[8];
#pragma unroll
            for (int j = 0; j < 8; j++)
                xv[j] = xr[lane + j * 32];
            float pl[4] = {0.f, 0.f, 0.f, 0.f};
#pragma unroll
            for (int j = 0; j < 8; j++)
#pragma unroll
                for (int l = 0; l < 4; l++)
                    pl[l] += dot4(xv[j], sV[l * 256 + lane + j * 32]);
#pragma unroll
            for (int o = 16; o > 0; o >>= 1)
#pragma unroll
                for (int l = 0; l < 4; l++)
                    pl[l] += __shfl_xor_sync(0xffffffffu, pl[l], o);
            if (lane == 0) {
                float a4 = 1.0f;
#pragma unroll
                for (int l = 0; l < 4; l++) {
                    float dd = pl[l] + cc[l];
                    a4 += a4 * dd + ee[l];
                }
                g_a4[r] = a4;
            }
        }
        __threadfence();
        __syncthreads();
        if (tid == 0) atomicAdd(&g_sync[1], 1);
        return;
    }

    // ================= GEMM CTA =================
    const int bn = bid & 15;          // 0..15
    const int bm = bid >> 4;          // 0..7
    const uint32_t sb = smem_u32(smem);
    const int warp_m = wid >> 1;      // 0..3 -> M offset 32*warp_m
    const int warp_n = wid & 1;       // 0..1 -> N offset 32*warp_n

    // ---- A load addressing: 128 rows x 16 granules = 2048, 8 per thread ----
    const char* pA[8]; uint32_t offA[8];
#pragma unroll
    for (int it = 0; it < 8; ++it) {
        int idx = tid + it * 256;
        int row = idx >> 4;          // 0..127 (m)
        int g   = idx & 15;          // 16B granule within 256B k-row
        size_t gb = ((size_t)(bm * GBM + row) * KDIM) * 2 + g * 16;
        pA[it] = (const char*)g_x16 + gb;
        offA[it] = (uint32_t)(g >> 3) * 16384 + swz(row * 128 + (g & 7) * 16);
    }
    // ---- B load addressing: 128 k-rows x 8 granules = 1024, 4 per thread ----
    const char* pB[4]; uint32_t offB[4];
#pragma unroll
    for (int it = 0; it < 4; ++it) {
        int idx = tid + it * 256;
        int row = idx >> 3;          // 0..127 (k)
        int g   = idx & 7;           // 16B granule within 128B n-row
        pB[it] = (const char*)g_w16 + (size_t)row * 2048 + bn * 128 + g * 16;
        offB[it] = swz(row * 128 + g * 16);
    }

    // ---- ldmatrix per-lane offset components ----
    const int a_row_l = lane & 15;
    const int a_kb_l  = (lane >> 4) << 4;
    const int b_krow_l = (lane & 7) + ((lane >> 3) & 1) * 8;
    const int b_nb_l   = (lane >> 4) << 4;    // +16 bytes = +8 n-cols

    float acc[2][4][4];
#pragma unroll
    for (int mi = 0; mi < 2; mi++)
#pragma unroll
        for (int ni = 0; ni < 4; ni++)
#pragma unroll
            for (int j = 0; j < 4; j++) acc[mi][ni][j] = 0.0f;

    // ---- wait for all converts, then start pipeline ----
    if (tid == 0) {
        while (atomicAdd(&g_sync[0], 0) < 16) { }
        __threadfence();
    }
    __syncthreads();

    // ---- prologue: preload chunk 0 into stage 0 ----
#pragma unroll
    for (int it = 0; it < 8; ++it)
        cp_async16(sb + SUB_A + offA[it], pA[it]);
#pragma unroll
    for (int it = 0; it < 4; ++it)
        cp_async16(sb + SUB_B + offB[it], pB[it]);
    asm volatile("cp.async.commit_group;" ::: "memory");

    for (int c = 0; c < NCHUNK; ++c) {
        asm volatile("cp.async.wait_group 0;" ::: "memory");
        __syncthreads();

        if (c + 1 < NCHUNK) {
            uint32_t dst = sb + ((c + 1) & 1) * STAGE_BYTES;
            size_t goA = (size_t)(c + 1) * 256;        // +128 k fp16 along row
            size_t goB = (size_t)(c + 1) * 262144;     // +128 k-rows of 2048B
#pragma unroll
            for (int it = 0; it < 8; ++it)
                cp_async16(dst + SUB_A + offA[it], pA[it] + goA);
#pragma unroll
            for (int it = 0; it < 4; ++it)
                cp_async16(dst + SUB_B + offB[it], pB[it] + goB);
            asm volatile("cp.async.commit_group;" ::: "memory");
        }

        const uint32_t base = sb + (c & 1) * STAGE_BYTES;
#pragma unroll
        for (int sub = 0; sub < 2; sub++) {
            const uint32_t baseA = base + SUB_A + sub * 16384;
            const uint32_t baseB = base + SUB_B;
            const int ksub = sub * 64;
#pragma unroll
            for (int kk = 0; kk < 4; kk++) {
                uint32_t RA[2][4], RB[8];
#pragma unroll
                for (int mi = 0; mi < 2; mi++) {
                    int row = warp_m * 32 + mi * 16 + a_row_l;
                    uint32_t off = swz(row * 128 + kk * 32 + a_kb_l);
                    ldsm_x4(RA[mi], baseA + off);
                }
#pragma unroll
                for (int p = 0; p < 2; p++) {
                    int krow = ksub + kk * 16 + b_krow_l;
                    int nb   = (warp_n * 32 + p * 16) * 2 + b_nb_l;
                    uint32_t off = swz(krow * 128 + nb);
                    ldsm_x4_t(&RB[4 * p], baseB + off);
                }
#pragma unroll
                for (int mi = 0; mi < 2; mi++)
#pragma unroll
                    for (int ni = 0; ni < 4; ni++)
                        mma_f16(acc[mi][ni], RA[mi], &RB[2 * ni]);
            }
        }
        __syncthreads();
    }

    // ---- wait for a4 (producers finished long ago in practice) ----
    if (tid == 0) {
        while (atomicAdd(&g_sync[1], 0) < 16) { }
        __threadfence();
    }
    __syncthreads();

    // ---- fused epilogue: out = a4(row) * (acc + bias) + u4(col) ----
    const int g = lane >> 2;
    const int t = lane & 3;
#pragma unroll
    for (int mi = 0; mi < 2; mi++) {
        int row0 = bm * GBM + warp_m * 32 + mi * 16 + g;
        float aR0 = g_a4[row0];
        float aR8 = g_a4[row0 + 8];
#pragma unroll
        for (int ni = 0; ni < 4; ni++) {
            int col = bn * GBN + warp_n * 32 + ni * 8 + t * 2;
            float b0 = bias[col];
            float b1 = bias[col + 1];
            float u0 = g_u4[col];
            float u1 = g_u4[col + 1];
            float2 v0, v1;
            v0.x = fmaf(aR0, acc[mi][ni][0] + b0, u0);
            v0.y = fmaf(aR0, acc[mi][ni][1] + b1, u1);
            v1.x = fmaf(aR8, acc[mi][ni][2] + b0, u0);
            v1.y = fmaf(aR8, acc[mi][ni][3] + b1, u1);
            *(float2*)(out + (size_t)row0 * HDIM + col) = v0;
            *(float2*)(out + (size_t)(row0 + 8) * HDIM + col) = v1;
        }
    }
}

// ---------------------------------------------------------------------------
extern "C" void kernel_launch(void* const* d_in, const int* in_sizes, int n_in,
                              void* d_out, int out_size)
{
    const float* x     = (const float*)d_in[0];
    const float* W_enc = (const float*)d_in[1];
    const float* b_enc = (const float*)d_in[2];
    const float* ws    = (const float*)d_in[3];
    const float* bs    = (const float*)d_in[4];
    float* out = (float*)d_out;

    cudaFuncSetAttribute(fused_kernel,
                         cudaFuncAttributeMaxDynamicSharedMemorySize, GEMM_SMEM);

    setup_kernel<<<1, 256>>>(b_enc, ws, bs);
    fused_kernel<<<144, 256, GEMM_SMEM>>>(b_enc, x, W_enc, ws, out);
}

// round 17
// speedup vs baseline: 1.1643x; 1.1643x over previous
#include <cuda_runtime.h>
#include <cuda_fp16.h>
#include <cstdint>

// ---------------------------------------------------------------------------
// CrossNetLayer on GB300 (sm_103a; PTX target compute_103 -> no tcgen05)
//   h = x @ W_enc + b_enc  -> mma.sync fp16 GEMM, fp32 accum,
//        with ON-THE-FLY fp32->fp16 conversion in the GEMM load stage
//        (no precompute pass over x / W at all).
//   cross layers closed-form, folded into the GEMM epilogue:
//     V_l = W @ w_l ; c_l = b_enc . w_l ; e_l = u_l . w_l ; u4 = sum b_l
//     d_l(row) = x_row . V_l + c_l ;  a <- a + a*d_l + e_l (a0=1)
//     out = a4 * h + u4
// Grid 144 = 128 GEMM CTAs (128x64 tiles) + 16 producer CTAs (V then a4).
// ---------------------------------------------------------------------------

#define BDIM 1024
#define HDIM 1024
#define KDIM 1024
#define DEPTH 4

// Scratch (no cudaMalloc allowed)
__device__ float   g_V[DEPTH * KDIM];    // V[l][k] = W[k,:].w_l   (fp32)
__device__ float   g_e[DEPTH];           // e_l = u_l . w_l
__device__ float   g_c[DEPTH];           // c_l = b_enc . w_l
__device__ float   g_u4[HDIM];           // u4 = b0+b1+b2+b3
__device__ float   g_a4[BDIM];           // per-row output scale
__device__ int     g_sync[2];            // [0]=V_done, [1]=a4_done

// ---------------------------------------------------------------------------
// helpers
// ---------------------------------------------------------------------------
__device__ __forceinline__ uint32_t smem_u32(const void* p) {
    uint32_t a;
    asm("{ .reg .u64 t; cvta.to.shared.u64 t, %1; cvt.u32.u64 %0, t; }"
        : "=r"(a) : "l"(p));
    return a;
}

__device__ __forceinline__ uint32_t swz(uint32_t off) {
    return off ^ ((off >> 3) & 0x70);   // SW128: 16B granule ^= row&7
}

__device__ __forceinline__ void ldsm_x4(uint32_t* r, uint32_t addr) {
    asm volatile("ldmatrix.sync.aligned.m8n8.x4.shared.b16 {%0,%1,%2,%3}, [%4];"
                 : "=r"(r[0]), "=r"(r[1]), "=r"(r[2]), "=r"(r[3]) : "r"(addr));
}

__device__ __forceinline__ void ldsm_x4_t(uint32_t* r, uint32_t addr) {
    asm volatile("ldmatrix.sync.aligned.m8n8.x4.trans.shared.b16 {%0,%1,%2,%3}, [%4];"
                 : "=r"(r[0]), "=r"(r[1]), "=r"(r[2]), "=r"(r[3]) : "r"(addr));
}

__device__ __forceinline__ void mma_f16(float* d, const uint32_t* a, const uint32_t* b) {
    asm volatile(
        "mma.sync.aligned.m16n8k16.row.col.f32.f16.f16.f32 "
        "{%0,%1,%2,%3}, {%4,%5,%6,%7}, {%8,%9}, {%0,%1,%2,%3};"
        : "+f"(d[0]), "+f"(d[1]), "+f"(d[2]), "+f"(d[3])
        : "r"(a[0]), "r"(a[1]), "r"(a[2]), "r"(a[3]), "r"(b[0]), "r"(b[1]));
}

__device__ __forceinline__ float dot4(float4 a, float4 b) {
    return a.x * b.x + a.y * b.y + a.z * b.z + a.w * b.w;
}

// pack 8 fp32 (two float4) into 8 fp16 (one uint4)
__device__ __forceinline__ uint4 cvt8(float4 a, float4 b) {
    __half2 h0 = __floats2half2_rn(a.x, a.y);
    __half2 h1 = __floats2half2_rn(a.z, a.w);
    __half2 h2 = __floats2half2_rn(b.x, b.y);
    __half2 h3 = __floats2half2_rn(b.z, b.w);
    uint4 u;
    u.x = *(uint32_t*)&h0;
    u.y = *(uint32_t*)&h1;
    u.z = *(uint32_t*)&h2;
    u.w = *(uint32_t*)&h3;
    return u;
}

// ---------------------------------------------------------------------------
// setup_kernel: 1 block x 256 threads — zero sync counters; compute c,e,u4.
// ---------------------------------------------------------------------------
__global__ __launch_bounds__(256, 1) void setup_kernel(
    const float* __restrict__ b_enc,
    const float* __restrict__ ws, const float* __restrict__ bs)
{
    __shared__ float red[8][8];
    const int tid  = threadIdx.x;
    const int lane = tid & 31;
    const int wid  = tid >> 5;

    if (tid < 2) g_sync[tid] = 0;

    float r[7];   // c0,c1,c2,c3,e1,e2,e3
#pragma unroll
    for (int i = 0; i < 7; i++) r[i] = 0.f;
#pragma unroll
    for (int j = 0; j < 4; j++) {
        int c = tid * 4 + j;
        float be = b_enc[c];
        float b0 = bs[0 * HDIM + c];
        float b1 = bs[1 * HDIM + c];
        float b2 = bs[2 * HDIM + c];
        float b3 = bs[3 * HDIM + c];
        float w0 = ws[0 * HDIM + c];
        float w1 = ws[1 * HDIM + c];
        float w2 = ws[2 * HDIM + c];
        float w3 = ws[3 * HDIM + c];
        r[0] += be * w0;
        r[1] += be * w1;
        r[2] += be * w2;
        r[3] += be * w3;
        r[4] += b0 * w1;
        r[5] += (b0 + b1) * w2;
        r[6] += (b0 + b1 + b2) * w3;
        g_u4[c] = b0 + b1 + b2 + b3;
    }
#pragma unroll
    for (int o = 16; o > 0; o >>= 1)
#pragma unroll
        for (int i = 0; i < 7; i++)
            r[i] += __shfl_xor_sync(0xffffffffu, r[i], o);
    if (lane == 0) {
#pragma unroll
        for (int i = 0; i < 7; i++) red[wid][i] = r[i];
    }
    __syncthreads();
    if (tid == 0) {
        float s[7];
#pragma unroll
        for (int i = 0; i < 7; i++) {
            s[i] = 0.f;
#pragma unroll
            for (int w = 0; w < 8; w++) s[i] += red[w][i];
        }
        g_c[0] = s[0]; g_c[1] = s[1]; g_c[2] = s[2]; g_c[3] = s[3];
        g_e[0] = 0.0f; g_e[1] = s[4]; g_e[2] = s[5]; g_e[3] = s[6];
    }
}

// ---------------------------------------------------------------------------
// Fused kernel: grid 144 x 256 threads, 48KB smem, 1 CTA/SM.
//   bid [0,128): GEMM, 128x64 tile, GKC=64, register-staged fp32->fp16 loads.
//   bid [128,144): producer p — V for k in [p*64,+64), barrier, a4 for rows.
// ---------------------------------------------------------------------------
#define GBM 128
#define GBN 64
#define GKC 64
#define NCHUNK (KDIM / GKC)     // 16

#define SUB_A 0
#define SUB_B 16384
#define STAGE_BYTES 24576
#define FUSED_SMEM (2 * STAGE_BYTES)   // 49152

__global__ __launch_bounds__(256, 1) void fused_kernel(
    const float* __restrict__ bias, const float* __restrict__ x,
    const float* __restrict__ W,    const float* __restrict__ ws,
    float* __restrict__ out)
{
    extern __shared__ char smem[];
    const int bid  = blockIdx.x;      // 0..143
    const int tid  = threadIdx.x;     // 0..255
    const int wid  = tid >> 5;        // 0..7
    const int lane = tid & 31;

    if (bid >= 128) {
        // ================= producer CTA =================
        const int p = bid - 128;      // 0..15

        // cache ws (16KB) in smem
        float4* sws = (float4*)smem;
        const float4* gws = (const float4*)ws;
#pragma unroll
        for (int i = 0; i < 4; i++)
            sws[tid + i * 256] = gws[tid + i * 256];
        __syncthreads();

        // ---- V[l][k] = W[k,:].w_l for k in [p*64, +64), 8 rows/warp ----
        {
            const float4* Wb = (const float4*)W;
            const int rbase = p * 64 + wid * 8;
#pragma unroll
            for (int it = 0; it < 8; it++) {
                const int r = rbase + it;
                float4 a[8];
#pragma unroll
                for (int j = 0; j < 8; j++)
                    a[j] = Wb[(size_t)r * 256 + lane + j * 32];
                float pl[4] = {0.f, 0.f, 0.f, 0.f};
#pragma unroll
                for (int j = 0; j < 8; j++)
#pragma unroll
                    for (int l = 0; l < 4; l++)
                        pl[l] += dot4(a[j], sws[l * 256 + lane + j * 32]);
#pragma unroll
                for (int o = 16; o > 0; o >>= 1)
#pragma unroll
                    for (int l = 0; l < 4; l++)
                        pl[l] += __shfl_xor_sync(0xffffffffu, pl[l], o);
                if (lane == 0) {
#pragma unroll
                    for (int l = 0; l < 4; l++)
                        g_V[l * KDIM + r] = pl[l];
                }
            }
        }

        __syncthreads();
        __threadfence();
        if (tid == 0) {
            atomicAdd(&g_sync[0], 1);
            while (atomicAdd(&g_sync[0], 0) < 16) { }
        }
        __syncthreads();
        __threadfence();

        // ---- a4 for rows [p*64, +64): V complete ----
        float4* sV = (float4*)smem;   // reuse smem
        const float4* gV = (const float4*)g_V;
        __syncthreads();
#pragma unroll
        for (int i = 0; i < 4; i++)
            sV[tid + i * 256] = gV[tid + i * 256];
        __syncthreads();

        float cc[4], ee[4];
#pragma unroll
        for (int l = 0; l < 4; l++) { cc[l] = g_c[l]; ee[l] = g_e[l]; }

        const int rbase = p * 64 + wid * 8;
#pragma unroll
        for (int it = 0; it < 8; it++) {
            const int r = rbase + it;
            const float4* xr = (const float4*)(x + (size_t)r * KDIM);
            float4 xv[8];
#pragma unroll
            for (int j = 0; j < 8; j++)
                xv[j] = xr[lane + j * 32];
            float pl[4] = {0.f, 0.f, 0.f, 0.f};
#pragma unroll
            for (int j = 0; j < 8; j++)
#pragma unroll
                for (int l = 0; l < 4; l++)
                    pl[l] += dot4(xv[j], sV[l * 256 + lane + j * 32]);
#pragma unroll
            for (int o = 16; o > 0; o >>= 1)
#pragma unroll
                for (int l = 0; l < 4; l++)
                    pl[l] += __shfl_xor_sync(0xffffffffu, pl[l], o);
            if (lane == 0) {
                float a4 = 1.0f;
#pragma unroll
                for (int l = 0; l < 4; l++) {
                    float dd = pl[l] + cc[l];
                    a4 += a4 * dd + ee[l];
                }
                g_a4[r] = a4;
            }
        }
        __threadfence();
        __syncthreads();
        if (tid == 0) atomicAdd(&g_sync[1], 1);
        return;
    }

    // ================= GEMM CTA =================
    const int bn = bid & 15;          // 0..15
    const int bm = bid >> 4;          // 0..7
    const uint32_t sb = smem_u32(smem);
    const int warp_m = wid >> 1;      // 0..3 -> M offset 32*warp_m
    const int warp_n = wid & 1;       // 0..1 -> N offset 32*warp_n

    // ---- A addressing: 128 rows x 8 granules (8 fp32 each) = 1024, 4/thread
    const float* pAf[4]; uint32_t offA[4];
#pragma unroll
    for (int it = 0; it < 4; ++it) {
        int idx = tid + it * 256;
        int row = idx >> 3;          // 0..127 (m)
        int g   = idx & 7;           // granule (8 k-values)
        pAf[it] = x + (size_t)(bm * GBM + row) * KDIM + g * 8;
        offA[it] = swz(row * 128 + g * 16);
    }
    // ---- B addressing: 64 k-rows x 8 granules = 512, 2/thread
    const float* pBf[2]; uint32_t offB[2];
#pragma unroll
    for (int it = 0; it < 2; ++it) {
        int idx = tid + it * 256;
        int kr  = idx >> 3;          // 0..63 (k)
        int g   = idx & 7;           // granule (8 n-values)
        pBf[it] = W + (size_t)kr * HDIM + bn * 64 + g * 8;
        offB[it] = swz(kr * 128 + g * 16);
    }

    // ---- ldmatrix per-lane offset components ----
    const int a_row_l = lane & 15;
    const int a_kb_l  = (lane >> 4) << 4;
    const int b_krow_l = (lane & 7) + ((lane >> 3) & 1) * 8;
    const int b_nb_l   = (lane >> 4) << 4;    // +16 bytes = +8 n-cols

    float acc[2][4][4];
#pragma unroll
    for (int mi = 0; mi < 2; mi++)
#pragma unroll
        for (int ni = 0; ni < 4; ni++)
#pragma unroll
            for (int j = 0; j < 4; j++) acc[mi][ni][j] = 0.0f;

    float4 rA[8], rB[4];   // register staging for one chunk (fp32)

    // ---- prologue: load chunk 0, convert, store to stage 0 ----
#pragma unroll
    for (int it = 0; it < 4; ++it) {
        rA[2 * it]     = *(const float4*)(pAf[it]);
        rA[2 * it + 1] = *(const float4*)(pAf[it] + 4);
    }
#pragma unroll
    for (int it = 0; it < 2; ++it) {
        rB[2 * it]     = *(const float4*)(pBf[it]);
        rB[2 * it + 1] = *(const float4*)(pBf[it] + 4);
    }
#pragma unroll
    for (int it = 0; it < 4; ++it)
        *(uint4*)(smem + SUB_A + offA[it]) = cvt8(rA[2 * it], rA[2 * it + 1]);
#pragma unroll
    for (int it = 0; it < 2; ++it)
        *(uint4*)(smem + SUB_B + offB[it]) = cvt8(rB[2 * it], rB[2 * it + 1]);
    __syncthreads();

    for (int c = 0; c < NCHUNK; ++c) {
        // issue fp32 loads for chunk c+1 (front-batched, MLP=12)
        if (c + 1 < NCHUNK) {
            const size_t goA = (size_t)(c + 1) * GKC;            // +64 floats
            const size_t goB = (size_t)(c + 1) * GKC * HDIM;     // +64 k-rows
#pragma unroll
            for (int it = 0; it < 4; ++it) {
                rA[2 * it]     = *(const float4*)(pAf[it] + goA);
                rA[2 * it + 1] = *(const float4*)(pAf[it] + goA + 4);
            }
#pragma unroll
            for (int it = 0; it < 2; ++it) {
                rB[2 * it]     = *(const float4*)(pBf[it] + goB);
                rB[2 * it + 1] = *(const float4*)(pBf[it] + goB + 4);
            }
        }

        // compute on chunk c (stage c&1)
        const uint32_t base = sb + (c & 1) * STAGE_BYTES;
        const uint32_t baseA = base + SUB_A;
        const uint32_t baseB = base + SUB_B;
#pragma unroll
        for (int kk = 0; kk < 4; kk++) {
            uint32_t RA[2][4], RB[8];
#pragma unroll
            for (int mi = 0; mi < 2; mi++) {
                int row = warp_m * 32 + mi * 16 + a_row_l;
                uint32_t off = swz(row * 128 + kk * 32 + a_kb_l);
                ldsm_x4(RA[mi], baseA + off);
            }
#pragma unroll
            for (int p = 0; p < 2; p++) {
                int krow = kk * 16 + b_krow_l;
                int nb   = (warp_n * 32 + p * 16) * 2 + b_nb_l;
                uint32_t off = swz(krow * 128 + nb);
                ldsm_x4_t(&RB[4 * p], baseB + off);
            }
#pragma unroll
            for (int mi = 0; mi < 2; mi++)
#pragma unroll
                for (int ni = 0; ni < 4; ni++)
                    mma_f16(acc[mi][ni], RA[mi], &RB[2 * ni]);
        }

        // convert + store chunk c+1 into the other stage (free since c-1's sync)
        if (c + 1 < NCHUNK) {
            char* dst = smem + ((c + 1) & 1) * STAGE_BYTES;
#pragma unroll
            for (int it = 0; it < 4; ++it)
                *(uint4*)(dst + SUB_A + offA[it]) = cvt8(rA[2 * it], rA[2 * it + 1]);
#pragma unroll
            for (int it = 0; it < 2; ++it)
                *(uint4*)(dst + SUB_B + offB[it]) = cvt8(rB[2 * it], rB[2 * it + 1]);
        }
        __syncthreads();
    }

    // ---- wait for a4 producers (finished long ago in practice) ----
    if (tid == 0) {
        while (atomicAdd(&g_sync[1], 0) < 16) { }
        __threadfence();
    }
    __syncthreads();

    // ---- fused epilogue: out = a4(row) * (acc + bias) + u4(col) ----
    const int g = lane >> 2;
    const int t = lane & 3;
#pragma unroll
    for (int mi = 0; mi < 2; mi++) {
        int row0 = bm * GBM + warp_m * 32 + mi * 16 + g;
        float aR0 = g_a4[row0];
        float aR8 = g_a4[row0 + 8];
#pragma unroll
        for (int ni = 0; ni < 4; ni++) {
            int col = bn * GBN + warp_n * 32 + ni * 8 + t * 2;
            float b0 = bias[col];
            float b1 = bias[col + 1];
            float u0 = g_u4[col];
            float u1 = g_u4[col + 1];
            float2 v0, v1;
            v0.x = fmaf(aR0, acc[mi][ni][0] + b0, u0);
            v0.y = fmaf(aR0, acc[mi][ni][1] + b1, u1);
            v1.x = fmaf(aR8, acc[mi][ni][2] + b0, u0);
            v1.y = fmaf(aR8, acc[mi][ni][3] + b1, u1);
            *(float2*)(out + (size_t)row0 * HDIM + col) = v0;
            *(float2*)(out + (size_t)(row0 + 8) * HDIM + col) = v1;
        }
    }
}

// ---------------------------------------------------------------------------
extern "C" void kernel_launch(void* const* d_in, const int* in_sizes, int n_in,
                              void* d_out, int out_size)
{
    const float* x     = (const float*)d_in[0];
    const float* W_enc = (const float*)d_in[1];
    const float* b_enc = (const float*)d_in[2];
    const float* ws    = (const float*)d_in[3];
    const float* bs    = (const float*)d_in[4];
    float* out = (float*)d_out;

    cudaFuncSetAttribute(fused_kernel,
                         cudaFuncAttributeMaxDynamicSharedMemorySize, FUSED_SMEM);

    setup_kernel<<<1, 256>>>(b_enc, ws, bs);
    fused_kernel<<<144, 256, FUSED_SMEM>>>(b_enc, x, W_enc, ws, out);
}